// round 8
// baseline (speedup 1.0000x reference)
#include <cuda_runtime.h>
#include <cuda_fp16.h>
#include <math.h>

#define BATCH 32
#define HW    1024
#define NTOT  32768
#define KCA   2304            // 9*256
#define KCB   6400            // 25*256

// ---------------- scratch ----------------
__device__ __half g_S[(size_t)NTOT * KCB];            // deform-sampled plane (419 MB)
__device__ __half g_xTh[(size_t)BATCH * HW * 256];    // NHWC fp16 activations
__device__ float g_out[(size_t)BATCH * 256 * HW];     // intermediate NCHW fp32
__device__ float g_offb[(size_t)BATCH * 50 * HW];
__device__ __half g_wch[(size_t)384 * KCA], g_wcl[(size_t)384 * KCA];
__device__ __half g_w3h[(size_t)256 * KCB], g_w3l[(size_t)256 * KCB];
__device__ __half g_w2h[(size_t)256 * KCA], g_w2l[(size_t)256 * KCA];
__device__ float g_bn[6 * 256];

// ---------------- helpers ----------------
__device__ __forceinline__ unsigned s2u(const void* p) {
    unsigned a;
    asm("{ .reg .u64 t; cvta.to.shared.u64 t, %1; cvt.u32.u64 %0, t; }" : "=r"(a) : "l"(p));
    return a;
}
__device__ __forceinline__ uint4 pack8h(const float* v) {
    unsigned r[4];
#pragma unroll
    for (int i = 0; i < 4; i++) {
        __half2 hp = __floats2half2_rn(v[2 * i], v[2 * i + 1]);
        r[i] = *(unsigned*)&hp;
    }
    return make_uint4(r[0], r[1], r[2], r[3]);
}

// ---------------- prep kernels ----------------
__global__ void prep_bn(const float* g1, const float* b1, const float* m1, const float* v1,
                        const float* g3, const float* b3, const float* m3, const float* v3,
                        const float* g2, const float* b2, const float* m2, const float* v2) {
    int i = threadIdx.x;
    float s1 = g1[i] * rsqrtf(v1[i] + 1e-5f);
    g_bn[i] = s1;          g_bn[256 + i] = b1[i] - m1[i] * s1;
    float s3 = g3[i] * rsqrtf(v3[i] + 1e-5f);
    g_bn[512 + i] = s3;    g_bn[768 + i] = b3[i] - m3[i] * s3;
    float s2 = g2[i] * rsqrtf(v2[i] + 1e-5f);
    g_bn[1024 + i] = s2;   g_bn[1280 + i] = b2[i] - m2[i] * s2;
}

__global__ void reorder_w_f16(const float* __restrict__ w, __half* __restrict__ Wh,
                              __half* __restrict__ Wl, int Ov, int T, int rowoff) {
    int idx = blockIdx.x * 256 + threadIdx.x;
    int c = idx & 255;
    int t = (idx >> 8) % T;
    int o = idx / (256 * T);
    float v = (o < Ov) ? w[((size_t)(o * 256 + c)) * T + t] : 0.f;
    __half h = __float2half_rn(v);
    __half l = __float2half_rn(v - __half2float(h));
    size_t a = (size_t)(rowoff + o) * (T * 256) + t * 256 + c;
    Wh[a] = h; Wl[a] = l;
}

// NCHW fp32 -> NHWC fp16
__global__ void transpose_cl(const float* __restrict__ in, __half* __restrict__ out) {
    __shared__ float tile[32][33];
    int b = blockIdx.z, c0 = blockIdx.y * 32, p0 = blockIdx.x * 32;
    int tx = threadIdx.x, ty = threadIdx.y;
    const float* ib = in + ((size_t)b << 18);
#pragma unroll
    for (int i = 0; i < 32; i += 8)
        tile[ty + i][tx] = ib[(size_t)(c0 + ty + i) * 1024 + p0 + tx];
    __syncthreads();
    __half* ob = out + ((size_t)b << 18);
#pragma unroll
    for (int i = 0; i < 32; i += 8)
        ob[(size_t)(p0 + ty + i) * 256 + c0 + tx] = __float2half_rn(tile[tx][ty + i]);
}

// deformable bilinear sampler: xTh (NHWC fp16) -> S[n][k] fp16
__global__ void sampler_f16(const __half* __restrict__ xT, const float* __restrict__ off,
                            __half* __restrict__ S) {
    int idx = blockIdx.x * 256 + threadIdx.x;     // NTOT*25*32
    int c8 = idx & 31;
    int k  = (idx >> 5) % 25;
    int n  = idx / 800;
    int p = n & 1023, b = n >> 10;
    int ho = p >> 5, wo = p & 31;
    const float* ob = off + (size_t)b * (50 * 1024);
    float dy = ob[(2 * k) * 1024 + p];
    float dx = ob[(2 * k + 1) * 1024 + p];
    float py = (float)(ho - 2 + k / 5) + dy;
    float px = (float)(wo - 2 + k % 5) + dx;
    float y0f = floorf(py), x0f = floorf(px);
    float wy1 = py - y0f, wx1 = px - x0f;
    float wy0 = 1.f - wy1, wx0 = 1.f - wx1;
    int y0 = (int)y0f, x0 = (int)x0f, y1 = y0 + 1, x1 = x0 + 1;
    float w00 = ((unsigned)y0 < 32u && (unsigned)x0 < 32u) ? wy0 * wx0 : 0.f;
    float w01 = ((unsigned)y0 < 32u && (unsigned)x1 < 32u) ? wy0 * wx1 : 0.f;
    float w10 = ((unsigned)y1 < 32u && (unsigned)x0 < 32u) ? wy1 * wx0 : 0.f;
    float w11 = ((unsigned)y1 < 32u && (unsigned)x1 < 32u) ? wy1 * wx1 : 0.f;
    int cy0 = min(max(y0, 0), 31), cy1 = min(max(y1, 0), 31);
    int cx0 = min(max(x0, 0), 31), cx1 = min(max(x1, 0), 31);
    const __half* xb = xT + ((size_t)b << 18);
    uint4 u00 = *(const uint4*)(xb + (size_t)(cy0 * 32 + cx0) * 256 + c8 * 8);
    uint4 u01 = *(const uint4*)(xb + (size_t)(cy0 * 32 + cx1) * 256 + c8 * 8);
    uint4 u10 = *(const uint4*)(xb + (size_t)(cy1 * 32 + cx0) * 256 + c8 * 8);
    uint4 u11 = *(const uint4*)(xb + (size_t)(cy1 * 32 + cx1) * 256 + c8 * 8);
    const __half2* h00 = (const __half2*)&u00;
    const __half2* h01 = (const __half2*)&u01;
    const __half2* h10 = (const __half2*)&u10;
    const __half2* h11 = (const __half2*)&u11;
    float vs[8];
#pragma unroll
    for (int q = 0; q < 4; q++) {
        float2 a = __half22float2(h00[q]), c = __half22float2(h01[q]);
        float2 d = __half22float2(h10[q]), e = __half22float2(h11[q]);
        vs[q*2+0] = w00*a.x + w01*c.x + w10*d.x + w11*e.x;
        vs[q*2+1] = w00*a.y + w01*c.y + w10*d.y + w11*e.y;
    }
    *(uint4*)(S + (size_t)n * KCB + k * 256 + c8 * 8) = pack8h(vs);
}

// ---------------- mma.sync GEMM: C = (Wh + Wl)·B, fused epilogue ------------
// imp=1: B implicitly im2col'ed 3x3/pad1 from NHWC fp16 (Bsrc = xTh), Kc=2304
// imp=0: B = materialized S rows (Bsrc = S), stride Kc
// mode 0: rows<256 relu(bn)->outp; rows 256..305 +boff->offp
// mode 2: outp = aux + relu(bn(C))      mode 3: outp = relu(bn(C) + aux)
#define TSLOT 10240
#define GSMEM (9 * TSLOT)

__device__ __forceinline__ void ldsm4(unsigned* r, unsigned a) {
    asm volatile("ldmatrix.sync.aligned.m8n8.x4.shared.b16 {%0,%1,%2,%3}, [%4];"
                 : "=r"(r[0]), "=r"(r[1]), "=r"(r[2]), "=r"(r[3]) : "r"(a));
}
__device__ __forceinline__ void ldsm2(unsigned* r, unsigned a) {
    asm volatile("ldmatrix.sync.aligned.m8n8.x2.shared.b16 {%0,%1}, [%2];"
                 : "=r"(r[0]), "=r"(r[1]) : "r"(a));
}
__device__ __forceinline__ void mmaf16(float* d, const unsigned* a, const unsigned* b) {
    asm volatile("mma.sync.aligned.m16n8k16.row.col.f32.f16.f16.f32 "
                 "{%0,%1,%2,%3}, {%4,%5,%6,%7}, {%8,%9}, {%0,%1,%2,%3};"
                 : "+f"(d[0]), "+f"(d[1]), "+f"(d[2]), "+f"(d[3])
                 : "r"(a[0]), "r"(a[1]), "r"(a[2]), "r"(a[3]), "r"(b[0]), "r"(b[1]));
}

__global__ __launch_bounds__(256, 2) void gemm_tc(
    const __half* __restrict__ Wh, const __half* __restrict__ Wl,
    const __half* __restrict__ Bsrc, int Kc, int imp, int mode,
    const float* __restrict__ scale, const float* __restrict__ shift,
    const float* __restrict__ boff,
    const float* __restrict__ aux, float* __restrict__ outp, float* __restrict__ offp)
{
    extern __shared__ char sm[];
    unsigned sb = s2u(sm);
    int tid = threadIdx.x, wid = tid >> 5, lane = tid & 31;
    int m0 = blockIdx.x * 128;
    int n0 = blockIdx.y * 128;
    int bimg = n0 >> 10;
    int NSt = Kc >> 5;

    float acc[4][4][4];
#pragma unroll
    for (int i = 0; i < 4; i++)
#pragma unroll
        for (int j = 0; j < 4; j++) {
            acc[i][j][0] = 0.f; acc[i][j][1] = 0.f; acc[i][j][2] = 0.f; acc[i][j][3] = 0.f;
        }

    // stage loader
    auto load_stage = [&](int s) {
        int kk = s << 5;
        int bufi = s % 3;
        for (int u = tid; u < 1536; u += 256) {
            int tile = u >> 9, v = u & 511, row = v >> 2, ch = v & 3;
            unsigned sa = sb + (unsigned)(tile * 3 + bufi) * TSLOT + row * 80 + ch * 16;
            if (tile < 2) {
                const __half* g = (tile ? Wl : Wh) + (size_t)(m0 + row) * Kc + kk + ch * 8;
                asm volatile("cp.async.cg.shared.global [%0], [%1], 16;" :: "r"(sa), "l"(g));
            } else if (!imp) {
                const __half* g = Bsrc + (size_t)(n0 + row) * Kc + kk + ch * 8;
                asm volatile("cp.async.cg.shared.global [%0], [%1], 16;" :: "r"(sa), "l"(g));
            } else {
                int k = kk + ch * 8;
                int t = k >> 8, c0 = k & 255;
                int p = (n0 & 1023) + row;
                int y = (p >> 5) - 1 + t / 3;
                int xx = (p & 31) - 1 + t % 3;
                int valid = ((unsigned)y < 32u) && ((unsigned)xx < 32u);
                int yc = min(max(y, 0), 31), xc = min(max(xx, 0), 31);
                const __half* g = Bsrc + (((size_t)bimg << 10) + yc * 32 + xc) * 256 + c0;
                int sz = valid ? 16 : 0;
                asm volatile("cp.async.cg.shared.global [%0], [%1], 16, %2;"
                             :: "r"(sa), "l"(g), "r"(sz));
            }
        }
        asm volatile("cp.async.commit_group;");
    };

    load_stage(0);
    load_stage(1);

    int warpM = wid >> 2, warpN = wid & 3;
    for (int s = 0; s < NSt; s++) {
        asm volatile("cp.async.wait_group 1;");
        __syncthreads();
        if (s + 2 < NSt) load_stage(s + 2);
        else asm volatile("cp.async.commit_group;");
        int buf = s % 3;
        unsigned bW0 = sb + (unsigned)(0 * 3 + buf) * TSLOT;
        unsigned bW1 = sb + (unsigned)(1 * 3 + buf) * TSLOT;
        unsigned bS  = sb + (unsigned)(2 * 3 + buf) * TSLOT;
#pragma unroll
        for (int ks = 0; ks < 2; ks++) {
            unsigned kb = ks * 32;
            unsigned bf[4][2];
            unsigned bo = (unsigned)(warpN * 32 + (lane & 7)) * 80 + kb + (((lane >> 3) & 1) * 16);
#pragma unroll
            for (int ni = 0; ni < 4; ni++) ldsm2(bf[ni], bS + bo + ni * (8 * 80));
            unsigned ao = (unsigned)(warpM * 64 + (lane & 15)) * 80 + kb + ((lane >> 4) * 16);
#pragma unroll
            for (int term = 0; term < 2; term++) {
                unsigned base = term ? bW1 : bW0;
                unsigned a[4][4];
#pragma unroll
                for (int mi = 0; mi < 4; mi++) ldsm4(a[mi], base + ao + mi * (16 * 80));
#pragma unroll
                for (int mi = 0; mi < 4; mi++)
#pragma unroll
                    for (int ni = 0; ni < 4; ni++) mmaf16(acc[mi][ni], a[mi], bf[ni]);
            }
        }
        __syncthreads();
    }

    // epilogue
    int g = lane >> 2, cp2 = (lane & 3) * 2;
    int pix0 = (n0 & 1023) + warpN * 32 + cp2;
#pragma unroll
    for (int mi = 0; mi < 4; mi++) {
#pragma unroll
        for (int h8 = 0; h8 < 2; h8++) {
            int row = m0 + warpM * 64 + mi * 16 + g + h8 * 8;
            if (mode == 0 && row >= 256) {
                int r2 = row - 256;
                if (r2 < 50) {
                    float bias = boff[r2];
                    float* dst = offp + ((size_t)bimg * 50 + r2) * 1024;
#pragma unroll
                    for (int ni = 0; ni < 4; ni++) {
                        float2 v;
                        v.x = acc[mi][ni][h8 * 2 + 0] + bias;
                        v.y = acc[mi][ni][h8 * 2 + 1] + bias;
                        *(float2*)(dst + pix0 + ni * 8) = v;
                    }
                }
            } else {
                float sc = scale[row], sh = shift[row];
                size_t base = ((size_t)bimg * 256 + row) * 1024;
#pragma unroll
                for (int ni = 0; ni < 4; ni++) {
                    float2 v;
                    v.x = fmaf(acc[mi][ni][h8 * 2 + 0], sc, sh);
                    v.y = fmaf(acc[mi][ni][h8 * 2 + 1], sc, sh);
                    size_t o = base + pix0 + ni * 8;
                    if (mode == 0) {
                        v.x = fmaxf(v.x, 0.f); v.y = fmaxf(v.y, 0.f);
                    } else if (mode == 2) {
                        float2 a = *(const float2*)(aux + o);
                        v.x = fmaxf(v.x, 0.f) + a.x; v.y = fmaxf(v.y, 0.f) + a.y;
                    } else {
                        float2 a = *(const float2*)(aux + o);
                        v.x = fmaxf(v.x + a.x, 0.f); v.y = fmaxf(v.y + a.y, 0.f);
                    }
                    *(float2*)(outp + o) = v;
                }
            }
        }
    }
}

// ---------------- launcher ----------------
extern "C" void kernel_launch(void* const* d_in, const int* in_sizes, int n_in,
                              void* d_out, int out_size) {
    const float* x     = (const float*)d_in[0];
    const float* w1    = (const float*)d_in[1];
    const float* w_off = (const float*)d_in[2];
    const float* b_off = (const float*)d_in[3];
    const float* w3    = (const float*)d_in[4];
    const float* w2    = (const float*)d_in[5];
    const float* g1 = (const float*)d_in[6],  *b1 = (const float*)d_in[7];
    const float* m1 = (const float*)d_in[8],  *v1 = (const float*)d_in[9];
    const float* g3 = (const float*)d_in[10], *b3 = (const float*)d_in[11];
    const float* m3 = (const float*)d_in[12], *v3 = (const float*)d_in[13];
    const float* g2 = (const float*)d_in[14], *b2 = (const float*)d_in[15];
    const float* m2 = (const float*)d_in[16], *v2 = (const float*)d_in[17];
    float* out = (float*)d_out;

    cudaFuncSetAttribute(gemm_tc, cudaFuncAttributeMaxDynamicSharedMemorySize, GSMEM);

    __half *S, *xTh, *wch, *wcl, *w3h, *w3l, *w2h, *w2l;
    float *gout, *goff, *bn;
    cudaGetSymbolAddress((void**)&S,    g_S);
    cudaGetSymbolAddress((void**)&xTh,  g_xTh);
    cudaGetSymbolAddress((void**)&gout, g_out);
    cudaGetSymbolAddress((void**)&goff, g_offb);
    cudaGetSymbolAddress((void**)&wch, g_wch);  cudaGetSymbolAddress((void**)&wcl, g_wcl);
    cudaGetSymbolAddress((void**)&w3h, g_w3h);  cudaGetSymbolAddress((void**)&w3l, g_w3l);
    cudaGetSymbolAddress((void**)&w2h, g_w2h);  cudaGetSymbolAddress((void**)&w2l, g_w2l);
    cudaGetSymbolAddress((void**)&bn,  g_bn);

    prep_bn<<<1, 256>>>(g1, b1, m1, v1, g3, b3, m3, v3, g2, b2, m2, v2);
    reorder_w_f16<<<2304, 256>>>(w1, wch, wcl, 256, 9, 0);
    reorder_w_f16<<<1152, 256>>>(w_off, wch, wcl, 50, 9, 256);
    reorder_w_f16<<<6400, 256>>>(w3, w3h, w3l, 256, 25, 0);
    reorder_w_f16<<<2304, 256>>>(w2, w2h, w2l, 256, 9, 0);

    transpose_cl<<<dim3(32, 8, 32), dim3(32, 8)>>>(x, xTh);

    // fused conv1 + offset conv (M=384), implicit im2col from xTh
    gemm_tc<<<dim3(3, 256), 256, GSMEM>>>(wch, wcl, xTh, KCA, 1, 0,
                                          bn, bn + 256, b_off, nullptr, gout, goff);
    // deformable sampling -> S
    sampler_f16<<<102400, 256>>>(xTh, goff, S);
    // deform conv: gout += relu(bn3)
    gemm_tc<<<dim3(2, 256), 256, GSMEM>>>(w3h, w3l, S, KCB, 0, 2,
                                          bn + 512, bn + 768, nullptr, gout, gout, nullptr);

    transpose_cl<<<dim3(32, 8, 32), dim3(32, 8)>>>(gout, xTh);
    // conv2: relu(bn2 + x) -> out, implicit im2col from xTh
    gemm_tc<<<dim3(2, 256), 256, GSMEM>>>(w2h, w2l, xTh, KCA, 1, 3,
                                          bn + 1024, bn + 1280, nullptr, x, out, nullptr);
}

// round 12
// speedup vs baseline: 1.8582x; 1.8582x over previous
#include <cuda_runtime.h>
#include <cuda_fp16.h>
#include <math.h>

#define BATCH 32
#define HW    1024
#define NTOT  32768
#define KCA   2304            // 9*256
#define KCB   6400            // 25*256

// ---------------- scratch ----------------
__device__ __half g_S[(size_t)NTOT * KCB];            // im2col / sampled plane
__device__ __half g_xTh[(size_t)BATCH * HW * 256];    // NHWC fp16 activations
__device__ float g_out[(size_t)BATCH * 256 * HW];
__device__ float g_offb[(size_t)BATCH * 50 * HW];
__device__ __half g_wch[(size_t)384 * KCA], g_wcl[(size_t)384 * KCA];
__device__ __half g_w3h[(size_t)256 * KCB], g_w3l[(size_t)256 * KCB];
__device__ __half g_w2h[(size_t)256 * KCA], g_w2l[(size_t)256 * KCA];
__device__ float g_bn[6 * 256];

// ---------------- helpers ----------------
__device__ __forceinline__ unsigned s2u(const void* p) {
    unsigned a;
    asm("{ .reg .u64 t; cvta.to.shared.u64 t, %1; cvt.u32.u64 %0, t; }" : "=r"(a) : "l"(p));
    return a;
}
__device__ __forceinline__ uint4 pack8h(const float* v) {
    unsigned r[4];
#pragma unroll
    for (int i = 0; i < 4; i++) {
        __half2 hp = __floats2half2_rn(v[2 * i], v[2 * i + 1]);
        r[i] = *(unsigned*)&hp;
    }
    return make_uint4(r[0], r[1], r[2], r[3]);
}

// ---------------- prep kernels ----------------
__global__ void prep_bn(const float* g1, const float* b1, const float* m1, const float* v1,
                        const float* g3, const float* b3, const float* m3, const float* v3,
                        const float* g2, const float* b2, const float* m2, const float* v2) {
    int i = threadIdx.x;
    float s1 = g1[i] * rsqrtf(v1[i] + 1e-5f);
    g_bn[i] = s1;          g_bn[256 + i] = b1[i] - m1[i] * s1;
    float s3 = g3[i] * rsqrtf(v3[i] + 1e-5f);
    g_bn[512 + i] = s3;    g_bn[768 + i] = b3[i] - m3[i] * s3;
    float s2 = g2[i] * rsqrtf(v2[i] + 1e-5f);
    g_bn[1024 + i] = s2;   g_bn[1280 + i] = b2[i] - m2[i] * s2;
}

__global__ void reorder_w_f16(const float* __restrict__ w, __half* __restrict__ Wh,
                              __half* __restrict__ Wl, int Ov, int T, int rowoff) {
    int idx = blockIdx.x * 256 + threadIdx.x;
    int c = idx & 255;
    int t = (idx >> 8) % T;
    int o = idx / (256 * T);
    float v = (o < Ov) ? w[((size_t)(o * 256 + c)) * T + t] : 0.f;
    __half h = __float2half_rn(v);
    __half l = __float2half_rn(v - __half2float(h));
    size_t a = (size_t)(rowoff + o) * (T * 256) + t * 256 + c;
    Wh[a] = h; Wl[a] = l;
}

// NCHW fp32 -> NHWC fp16
__global__ void transpose_cl(const float* __restrict__ in, __half* __restrict__ out) {
    __shared__ float tile[32][33];
    int b = blockIdx.z, c0 = blockIdx.y * 32, p0 = blockIdx.x * 32;
    int tx = threadIdx.x, ty = threadIdx.y;
    const float* ib = in + ((size_t)b << 18);
#pragma unroll
    for (int i = 0; i < 32; i += 8)
        tile[ty + i][tx] = ib[(size_t)(c0 + ty + i) * 1024 + p0 + tx];
    __syncthreads();
    __half* ob = out + ((size_t)b << 18);
#pragma unroll
    for (int i = 0; i < 32; i += 8)
        ob[(size_t)(p0 + ty + i) * 256 + c0 + tx] = __float2half_rn(tile[tx][ty + i]);
}

// im2col 3x3 pad1: xTh (NHWC fp16) -> S[n][k] — pure 16B gather-copy
__global__ void im2col_h(const __half* __restrict__ xT, __half* __restrict__ S) {
    int idx = blockIdx.x * 256 + threadIdx.x;     // NTOT*9*32
    int c8 = idx & 31;
    int t  = (idx >> 5) % 9;
    int n  = idx / 288;
    int p = n & 1023, b = n >> 10;
    int y = (p >> 5) - 1 + t / 3;
    int x = (p & 31) - 1 + t % 3;
    uint4 v = make_uint4(0, 0, 0, 0);
    if ((unsigned)y < 32u && (unsigned)x < 32u)
        v = *(const uint4*)(xT + ((size_t)b << 18) + (size_t)(y * 32 + x) * 256 + c8 * 8);
    *(uint4*)(S + (size_t)n * KCA + t * 256 + c8 * 8) = v;
}

// deformable bilinear sampler: xTh (NHWC fp16) -> S[n][k] fp16
__global__ void sampler_f16(const __half* __restrict__ xT, const float* __restrict__ off,
                            __half* __restrict__ S) {
    int idx = blockIdx.x * 256 + threadIdx.x;     // NTOT*25*32
    int c8 = idx & 31;
    int k  = (idx >> 5) % 25;
    int n  = idx / 800;
    int p = n & 1023, b = n >> 10;
    int ho = p >> 5, wo = p & 31;
    const float* ob = off + (size_t)b * (50 * 1024);
    float dy = ob[(2 * k) * 1024 + p];
    float dx = ob[(2 * k + 1) * 1024 + p];
    float py = (float)(ho - 2 + k / 5) + dy;
    float px = (float)(wo - 2 + k % 5) + dx;
    float y0f = floorf(py), x0f = floorf(px);
    float wy1 = py - y0f, wx1 = px - x0f;
    float wy0 = 1.f - wy1, wx0 = 1.f - wx1;
    int y0 = (int)y0f, x0 = (int)x0f, y1 = y0 + 1, x1 = x0 + 1;
    float w00 = ((unsigned)y0 < 32u && (unsigned)x0 < 32u) ? wy0 * wx0 : 0.f;
    float w01 = ((unsigned)y0 < 32u && (unsigned)x1 < 32u) ? wy0 * wx1 : 0.f;
    float w10 = ((unsigned)y1 < 32u && (unsigned)x0 < 32u) ? wy1 * wx0 : 0.f;
    float w11 = ((unsigned)y1 < 32u && (unsigned)x1 < 32u) ? wy1 * wx1 : 0.f;
    int cy0 = min(max(y0, 0), 31), cy1 = min(max(y1, 0), 31);
    int cx0 = min(max(x0, 0), 31), cx1 = min(max(x1, 0), 31);
    const __half* xb = xT + ((size_t)b << 18);
    uint4 u00 = *(const uint4*)(xb + (size_t)(cy0 * 32 + cx0) * 256 + c8 * 8);
    uint4 u01 = *(const uint4*)(xb + (size_t)(cy0 * 32 + cx1) * 256 + c8 * 8);
    uint4 u10 = *(const uint4*)(xb + (size_t)(cy1 * 32 + cx0) * 256 + c8 * 8);
    uint4 u11 = *(const uint4*)(xb + (size_t)(cy1 * 32 + cx1) * 256 + c8 * 8);
    const __half2* h00 = (const __half2*)&u00;
    const __half2* h01 = (const __half2*)&u01;
    const __half2* h10 = (const __half2*)&u10;
    const __half2* h11 = (const __half2*)&u11;
    float vs[8];
#pragma unroll
    for (int q = 0; q < 4; q++) {
        float2 a = __half22float2(h00[q]), c = __half22float2(h01[q]);
        float2 d = __half22float2(h10[q]), e = __half22float2(h11[q]);
        vs[q*2+0] = w00*a.x + w01*c.x + w10*d.x + w11*e.x;
        vs[q*2+1] = w00*a.y + w01*c.y + w10*d.y + w11*e.y;
    }
    *(uint4*)(S + (size_t)n * KCB + k * 256 + c8 * 8) = pack8h(vs);
}

// ---------------- mma.sync GEMM: C = (Wh [+ Wl]) · S, fused epilogue --------
// nterms: 2 = hi+lo weight terms, 1 = hi only
// mode 0: rows<256 relu(bn)->outp; rows 256..305 +boff->offp
// mode 2: outp = aux + relu(bn(C))      mode 3: outp = relu(bn(C) + aux)
#define TSLOT 10240                    // 128 rows * 80 bytes
#define GSMEM (6 * TSLOT)

__device__ __forceinline__ void ldsm4(unsigned* r, unsigned a) {
    asm volatile("ldmatrix.sync.aligned.m8n8.x4.shared.b16 {%0,%1,%2,%3}, [%4];"
                 : "=r"(r[0]), "=r"(r[1]), "=r"(r[2]), "=r"(r[3]) : "r"(a));
}
__device__ __forceinline__ void ldsm2(unsigned* r, unsigned a) {
    asm volatile("ldmatrix.sync.aligned.m8n8.x2.shared.b16 {%0,%1}, [%2];"
                 : "=r"(r[0]), "=r"(r[1]) : "r"(a));
}
__device__ __forceinline__ void mmaf16(float* d, const unsigned* a, const unsigned* b) {
    asm volatile("mma.sync.aligned.m16n8k16.row.col.f32.f16.f16.f32 "
                 "{%0,%1,%2,%3}, {%4,%5,%6,%7}, {%8,%9}, {%0,%1,%2,%3};"
                 : "+f"(d[0]), "+f"(d[1]), "+f"(d[2]), "+f"(d[3])
                 : "r"(a[0]), "r"(a[1]), "r"(a[2]), "r"(a[3]), "r"(b[0]), "r"(b[1]));
}

__global__ __launch_bounds__(256, 2) void gemm_tc(
    const __half* __restrict__ Wh, const __half* __restrict__ Wl,
    const __half* __restrict__ S, int Kc, int nterms, int mode,
    const float* __restrict__ scale, const float* __restrict__ shift,
    const float* __restrict__ boff,
    const float* __restrict__ aux, float* __restrict__ outp, float* __restrict__ offp)
{
    extern __shared__ char sm[];
    unsigned sb = s2u(sm);
    int tid = threadIdx.x, wid = tid >> 5, lane = tid & 31;
    int m0 = blockIdx.x * 128;
    int n0 = blockIdx.y * 128;

    float acc[4][4][4];
#pragma unroll
    for (int i = 0; i < 4; i++)
#pragma unroll
        for (int j = 0; j < 4; j++) {
            acc[i][j][0] = 0.f; acc[i][j][1] = 0.f; acc[i][j][2] = 0.f; acc[i][j][3] = 0.f;
        }

    const __half* gp[3] = {Wh, Wl, S};
    int NSt = Kc >> 5;

    // prologue
    for (int u = tid; u < 1536; u += 256) {
        int tile = u >> 9, v = u & 511, row = v >> 2, ch = v & 3;
        if (tile == 1 && nterms == 1) continue;
        int grow = (tile < 2) ? (m0 + row) : (n0 + row);
        const __half* g = gp[tile] + (size_t)grow * Kc + ch * 8;
        unsigned sa = sb + (unsigned)(tile * 2) * TSLOT + row * 80 + ch * 16;
        asm volatile("cp.async.cg.shared.global [%0], [%1], 16;" :: "r"(sa), "l"(g));
    }
    asm volatile("cp.async.commit_group;");

    int warpM = wid >> 2, warpN = wid & 3;
    for (int s = 0; s < NSt; s++) {
        int buf = s & 1;
        asm volatile("cp.async.wait_group 0;");
        __syncthreads();
        if (s + 1 < NSt) {
            int kk = (s + 1) << 5;
            for (int u = tid; u < 1536; u += 256) {
                int tile = u >> 9, v = u & 511, row = v >> 2, ch = v & 3;
                if (tile == 1 && nterms == 1) continue;
                int grow = (tile < 2) ? (m0 + row) : (n0 + row);
                const __half* g = gp[tile] + (size_t)grow * Kc + kk + ch * 8;
                unsigned sa = sb + (unsigned)(tile * 2 + (buf ^ 1)) * TSLOT + row * 80 + ch * 16;
                asm volatile("cp.async.cg.shared.global [%0], [%1], 16;" :: "r"(sa), "l"(g));
            }
            asm volatile("cp.async.commit_group;");
        }
        unsigned bW0 = sb + (unsigned)(0 * 2 + buf) * TSLOT;
        unsigned bW1 = sb + (unsigned)(1 * 2 + buf) * TSLOT;
        unsigned bS  = sb + (unsigned)(2 * 2 + buf) * TSLOT;
#pragma unroll
        for (int ks = 0; ks < 2; ks++) {
            unsigned kb = ks * 32;
            unsigned bf[4][2];
            unsigned bo = (unsigned)(warpN * 32 + (lane & 7)) * 80 + kb + (((lane >> 3) & 1) * 16);
#pragma unroll
            for (int ni = 0; ni < 4; ni++) ldsm2(bf[ni], bS + bo + ni * (8 * 80));
            unsigned ao = (unsigned)(warpM * 64 + (lane & 15)) * 80 + kb + ((lane >> 4) * 16);
            {
                unsigned a[4][4];
#pragma unroll
                for (int mi = 0; mi < 4; mi++) ldsm4(a[mi], bW0 + ao + mi * (16 * 80));
#pragma unroll
                for (int mi = 0; mi < 4; mi++)
#pragma unroll
                    for (int ni = 0; ni < 4; ni++) mmaf16(acc[mi][ni], a[mi], bf[ni]);
            }
            if (nterms == 2) {
                unsigned a[4][4];
#pragma unroll
                for (int mi = 0; mi < 4; mi++) ldsm4(a[mi], bW1 + ao + mi * (16 * 80));
#pragma unroll
                for (int mi = 0; mi < 4; mi++)
#pragma unroll
                    for (int ni = 0; ni < 4; ni++) mmaf16(acc[mi][ni], a[mi], bf[ni]);
            }
        }
        __syncthreads();
    }

    // epilogue
    int g = lane >> 2, cp2 = (lane & 3) * 2;
    int bimg = n0 >> 10;
    int pix0 = (n0 & 1023) + warpN * 32 + cp2;
#pragma unroll
    for (int mi = 0; mi < 4; mi++) {
#pragma unroll
        for (int h8 = 0; h8 < 2; h8++) {
            int row = m0 + warpM * 64 + mi * 16 + g + h8 * 8;
            if (mode == 0 && row >= 256) {
                int r2 = row - 256;
                if (r2 < 50) {
                    float bias = boff[r2];
                    float* dst = offp + ((size_t)bimg * 50 + r2) * 1024;
#pragma unroll
                    for (int ni = 0; ni < 4; ni++) {
                        float2 v;
                        v.x = acc[mi][ni][h8 * 2 + 0] + bias;
                        v.y = acc[mi][ni][h8 * 2 + 1] + bias;
                        *(float2*)(dst + pix0 + ni * 8) = v;
                    }
                }
            } else {
                float sc = scale[row], sh = shift[row];
                size_t base = ((size_t)bimg * 256 + row) * 1024;
#pragma unroll
                for (int ni = 0; ni < 4; ni++) {
                    float2 v;
                    v.x = fmaf(acc[mi][ni][h8 * 2 + 0], sc, sh);
                    v.y = fmaf(acc[mi][ni][h8 * 2 + 1], sc, sh);
                    size_t o = base + pix0 + ni * 8;
                    if (mode == 0) {
                        v.x = fmaxf(v.x, 0.f); v.y = fmaxf(v.y, 0.f);
                    } else if (mode == 2) {
                        float2 a = *(const float2*)(aux + o);
                        v.x = fmaxf(v.x, 0.f) + a.x; v.y = fmaxf(v.y, 0.f) + a.y;
                    } else {
                        float2 a = *(const float2*)(aux + o);
                        v.x = fmaxf(v.x + a.x, 0.f); v.y = fmaxf(v.y + a.y, 0.f);
                    }
                    *(float2*)(outp + o) = v;
                }
            }
        }
    }
}

// ---------------- launcher ----------------
extern "C" void kernel_launch(void* const* d_in, const int* in_sizes, int n_in,
                              void* d_out, int out_size) {
    const float* x     = (const float*)d_in[0];
    const float* w1    = (const float*)d_in[1];
    const float* w_off = (const float*)d_in[2];
    const float* b_off = (const float*)d_in[3];
    const float* w3    = (const float*)d_in[4];
    const float* w2    = (const float*)d_in[5];
    const float* g1 = (const float*)d_in[6],  *b1 = (const float*)d_in[7];
    const float* m1 = (const float*)d_in[8],  *v1 = (const float*)d_in[9];
    const float* g3 = (const float*)d_in[10], *b3 = (const float*)d_in[11];
    const float* m3 = (const float*)d_in[12], *v3 = (const float*)d_in[13];
    const float* g2 = (const float*)d_in[14], *b2 = (const float*)d_in[15];
    const float* m2 = (const float*)d_in[16], *v2 = (const float*)d_in[17];
    float* out = (float*)d_out;

    cudaFuncSetAttribute(gemm_tc, cudaFuncAttributeMaxDynamicSharedMemorySize, GSMEM);

    __half *S, *xTh, *wch, *wcl, *w3h, *w3l, *w2h, *w2l;
    float *gout, *goff, *bn;
    cudaGetSymbolAddress((void**)&S,    g_S);
    cudaGetSymbolAddress((void**)&xTh,  g_xTh);
    cudaGetSymbolAddress((void**)&gout, g_out);
    cudaGetSymbolAddress((void**)&goff, g_offb);
    cudaGetSymbolAddress((void**)&wch, g_wch);  cudaGetSymbolAddress((void**)&wcl, g_wcl);
    cudaGetSymbolAddress((void**)&w3h, g_w3h);  cudaGetSymbolAddress((void**)&w3l, g_w3l);
    cudaGetSymbolAddress((void**)&w2h, g_w2h);  cudaGetSymbolAddress((void**)&w2l, g_w2l);
    cudaGetSymbolAddress((void**)&bn,  g_bn);

    prep_bn<<<1, 256>>>(g1, b1, m1, v1, g3, b3, m3, v3, g2, b2, m2, v2);
    reorder_w_f16<<<2304, 256>>>(w1, wch, wcl, 256, 9, 0);
    reorder_w_f16<<<1152, 256>>>(w_off, wch, wcl, 50, 9, 256);
    reorder_w_f16<<<6400, 256>>>(w3, w3h, w3l, 256, 25, 0);
    reorder_w_f16<<<2304, 256>>>(w2, w2h, w2l, 256, 9, 0);

    transpose_cl<<<dim3(32, 8, 32), dim3(32, 8)>>>(x, xTh);
    im2col_h<<<36864, 256>>>(xTh, S);

    // fused conv1 + offset conv (M=384), 2-term weights
    gemm_tc<<<dim3(3, 256), 256, GSMEM>>>(wch, wcl, S, KCA, 2, 0,
                                          bn, bn + 256, b_off, nullptr, gout, goff);
    // deformable sampling -> S
    sampler_f16<<<102400, 256>>>(xTh, goff, S);
    // deform conv (1-term weights): gout += relu(bn3)
    gemm_tc<<<dim3(2, 256), 256, GSMEM>>>(w3h, w3l, S, KCB, 1, 2,
                                          bn + 512, bn + 768, nullptr, gout, gout, nullptr);

    transpose_cl<<<dim3(32, 8, 32), dim3(32, 8)>>>(gout, xTh);
    im2col_h<<<36864, 256>>>(xTh, S);
    // conv2 (2-term): relu(bn2 + x) -> out
    gemm_tc<<<dim3(2, 256), 256, GSMEM>>>(w2h, w2l, S, KCA, 2, 3,
                                          bn + 1024, bn + 1280, nullptr, x, out, nullptr);
}

// round 14
// speedup vs baseline: 2.2155x; 1.1923x over previous
#include <cuda_runtime.h>
#include <cuda_fp16.h>
#include <math.h>

#define BATCH 32
#define HW    1024
#define NTOT  32768
#define KCA   2304            // 9*256
#define KCB   6400            // 25*256

// ---------------- scratch ----------------
__device__ __half g_S[(size_t)NTOT * KCB];            // im2col / sampled plane
__device__ __half g_xTh[(size_t)BATCH * HW * 256];    // NHWC fp16 activations
__device__ float g_out[(size_t)BATCH * 256 * HW];
__device__ float g_offb[(size_t)BATCH * 50 * HW];
__device__ __half g_wch[(size_t)384 * KCA];
__device__ __half g_w3h[(size_t)256 * KCB];
__device__ __half g_w2h[(size_t)256 * KCA];
__device__ float g_bn[6 * 256];

// ---------------- helpers ----------------
__device__ __forceinline__ unsigned s2u(const void* p) {
    unsigned a;
    asm("{ .reg .u64 t; cvta.to.shared.u64 t, %1; cvt.u32.u64 %0, t; }" : "=r"(a) : "l"(p));
    return a;
}
__device__ __forceinline__ uint4 pack8h(const float* v) {
    unsigned r[4];
#pragma unroll
    for (int i = 0; i < 4; i++) {
        __half2 hp = __floats2half2_rn(v[2 * i], v[2 * i + 1]);
        r[i] = *(unsigned*)&hp;
    }
    return make_uint4(r[0], r[1], r[2], r[3]);
}

// ---------------- prep kernels ----------------
__global__ void prep_bn(const float* g1, const float* b1, const float* m1, const float* v1,
                        const float* g3, const float* b3, const float* m3, const float* v3,
                        const float* g2, const float* b2, const float* m2, const float* v2) {
    int i = threadIdx.x;
    float s1 = g1[i] * rsqrtf(v1[i] + 1e-5f);
    g_bn[i] = s1;          g_bn[256 + i] = b1[i] - m1[i] * s1;
    float s3 = g3[i] * rsqrtf(v3[i] + 1e-5f);
    g_bn[512 + i] = s3;    g_bn[768 + i] = b3[i] - m3[i] * s3;
    float s2 = g2[i] * rsqrtf(v2[i] + 1e-5f);
    g_bn[1024 + i] = s2;   g_bn[1280 + i] = b2[i] - m2[i] * s2;
}

// w[O][256][T] -> Wh[rowoff+o][t*256+c], fp16 (o >= Ov zero-padded)
__global__ void reorder_w_f16(const float* __restrict__ w, __half* __restrict__ Wh,
                              int Ov, int T, int rowoff) {
    int idx = blockIdx.x * 256 + threadIdx.x;
    int c = idx & 255;
    int t = (idx >> 8) % T;
    int o = idx / (256 * T);
    float v = (o < Ov) ? w[((size_t)(o * 256 + c)) * T + t] : 0.f;
    Wh[(size_t)(rowoff + o) * (T * 256) + t * 256 + c] = __float2half_rn(v);
}

// NCHW fp32 -> NHWC fp16
__global__ void transpose_cl(const float* __restrict__ in, __half* __restrict__ out) {
    __shared__ float tile[32][33];
    int b = blockIdx.z, c0 = blockIdx.y * 32, p0 = blockIdx.x * 32;
    int tx = threadIdx.x, ty = threadIdx.y;
    const float* ib = in + ((size_t)b << 18);
#pragma unroll
    for (int i = 0; i < 32; i += 8)
        tile[ty + i][tx] = ib[(size_t)(c0 + ty + i) * 1024 + p0 + tx];
    __syncthreads();
    __half* ob = out + ((size_t)b << 18);
#pragma unroll
    for (int i = 0; i < 32; i += 8)
        ob[(size_t)(p0 + ty + i) * 256 + c0 + tx] = __float2half_rn(tile[tx][ty + i]);
}

// im2col 3x3 pad1: xTh (NHWC fp16) -> S[n][k] — pure 16B gather-copy
__global__ void im2col_h(const __half* __restrict__ xT, __half* __restrict__ S) {
    int idx = blockIdx.x * 256 + threadIdx.x;     // NTOT*9*32
    int c8 = idx & 31;
    int t  = (idx >> 5) % 9;
    int n  = idx / 288;
    int p = n & 1023, b = n >> 10;
    int y = (p >> 5) - 1 + t / 3;
    int x = (p & 31) - 1 + t % 3;
    uint4 v = make_uint4(0, 0, 0, 0);
    if ((unsigned)y < 32u && (unsigned)x < 32u)
        v = *(const uint4*)(xT + ((size_t)b << 18) + (size_t)(y * 32 + x) * 256 + c8 * 8);
    *(uint4*)(S + (size_t)n * KCA + t * 256 + c8 * 8) = v;
}

// deformable bilinear sampler: xTh (NHWC fp16) -> S[n][k] fp16
__global__ void sampler_f16(const __half* __restrict__ xT, const float* __restrict__ off,
                            __half* __restrict__ S) {
    int idx = blockIdx.x * 256 + threadIdx.x;     // NTOT*25*32
    int c8 = idx & 31;
    int k  = (idx >> 5) % 25;
    int n  = idx / 800;
    int p = n & 1023, b = n >> 10;
    int ho = p >> 5, wo = p & 31;
    const float* ob = off + (size_t)b * (50 * 1024);
    float dy = ob[(2 * k) * 1024 + p];
    float dx = ob[(2 * k + 1) * 1024 + p];
    float py = (float)(ho - 2 + k / 5) + dy;
    float px = (float)(wo - 2 + k % 5) + dx;
    float y0f = floorf(py), x0f = floorf(px);
    float wy1 = py - y0f, wx1 = px - x0f;
    float wy0 = 1.f - wy1, wx0 = 1.f - wx1;
    int y0 = (int)y0f, x0 = (int)x0f, y1 = y0 + 1, x1 = x0 + 1;
    float w00 = ((unsigned)y0 < 32u && (unsigned)x0 < 32u) ? wy0 * wx0 : 0.f;
    float w01 = ((unsigned)y0 < 32u && (unsigned)x1 < 32u) ? wy0 * wx1 : 0.f;
    float w10 = ((unsigned)y1 < 32u && (unsigned)x0 < 32u) ? wy1 * wx0 : 0.f;
    float w11 = ((unsigned)y1 < 32u && (unsigned)x1 < 32u) ? wy1 * wx1 : 0.f;
    int cy0 = min(max(y0, 0), 31), cy1 = min(max(y1, 0), 31);
    int cx0 = min(max(x0, 0), 31), cx1 = min(max(x1, 0), 31);
    const __half* xb = xT + ((size_t)b << 18);
    uint4 u00 = *(const uint4*)(xb + (size_t)(cy0 * 32 + cx0) * 256 + c8 * 8);
    uint4 u01 = *(const uint4*)(xb + (size_t)(cy0 * 32 + cx1) * 256 + c8 * 8);
    uint4 u10 = *(const uint4*)(xb + (size_t)(cy1 * 32 + cx0) * 256 + c8 * 8);
    uint4 u11 = *(const uint4*)(xb + (size_t)(cy1 * 32 + cx1) * 256 + c8 * 8);
    const __half2* h00 = (const __half2*)&u00;
    const __half2* h01 = (const __half2*)&u01;
    const __half2* h10 = (const __half2*)&u10;
    const __half2* h11 = (const __half2*)&u11;
    float vs[8];
#pragma unroll
    for (int q = 0; q < 4; q++) {
        float2 a = __half22float2(h00[q]), c = __half22float2(h01[q]);
        float2 d = __half22float2(h10[q]), e = __half22float2(h11[q]);
        vs[q*2+0] = w00*a.x + w01*c.x + w10*d.x + w11*e.x;
        vs[q*2+1] = w00*a.y + w01*c.y + w10*d.y + w11*e.y;
    }
    *(uint4*)(S + (size_t)n * KCB + k * 256 + c8 * 8) = pack8h(vs);
}

// ---------------- mma.sync GEMM: C = Wh · S, fused epilogue -----------------
// mode 0: rows<256 relu(bn)->outp; rows 256..305 +boff->offp
// mode 2: outp = aux + relu(bn(C))      mode 3: outp = relu(bn(C) + aux)
#define TSLOT 10240                    // 128 rows * 80 bytes
#define GSMEM (4 * TSLOT)

__device__ __forceinline__ void ldsm4(unsigned* r, unsigned a) {
    asm volatile("ldmatrix.sync.aligned.m8n8.x4.shared.b16 {%0,%1,%2,%3}, [%4];"
                 : "=r"(r[0]), "=r"(r[1]), "=r"(r[2]), "=r"(r[3]) : "r"(a));
}
__device__ __forceinline__ void ldsm2(unsigned* r, unsigned a) {
    asm volatile("ldmatrix.sync.aligned.m8n8.x2.shared.b16 {%0,%1}, [%2];"
                 : "=r"(r[0]), "=r"(r[1]) : "r"(a));
}
__device__ __forceinline__ void mmaf16(float* d, const unsigned* a, const unsigned* b) {
    asm volatile("mma.sync.aligned.m16n8k16.row.col.f32.f16.f16.f32 "
                 "{%0,%1,%2,%3}, {%4,%5,%6,%7}, {%8,%9}, {%0,%1,%2,%3};"
                 : "+f"(d[0]), "+f"(d[1]), "+f"(d[2]), "+f"(d[3])
                 : "r"(a[0]), "r"(a[1]), "r"(a[2]), "r"(a[3]), "r"(b[0]), "r"(b[1]));
}

__global__ __launch_bounds__(256, 2) void gemm_tc(
    const __half* __restrict__ Wh, const __half* __restrict__ S,
    int Kc, int mode,
    const float* __restrict__ scale, const float* __restrict__ shift,
    const float* __restrict__ boff,
    const float* __restrict__ aux, float* __restrict__ outp, float* __restrict__ offp)
{
    extern __shared__ char sm[];
    unsigned sb = s2u(sm);
    int tid = threadIdx.x, wid = tid >> 5, lane = tid & 31;
    int m0 = blockIdx.x * 128;
    int n0 = blockIdx.y * 128;

    float acc[4][4][4];
#pragma unroll
    for (int i = 0; i < 4; i++)
#pragma unroll
        for (int j = 0; j < 4; j++) {
            acc[i][j][0] = 0.f; acc[i][j][1] = 0.f; acc[i][j][2] = 0.f; acc[i][j][3] = 0.f;
        }

    int NSt = Kc >> 5;

    // prologue: stage 0 -> buf 0 (tiles: 0 = W, 1 = S)
    for (int u = tid; u < 1024; u += 256) {
        int tile = u >> 9, v = u & 511, row = v >> 2, ch = v & 3;
        const __half* g = (tile ? S + (size_t)(n0 + row) * Kc
                                : Wh + (size_t)(m0 + row) * Kc) + ch * 8;
        unsigned sa = sb + (unsigned)(tile * 2) * TSLOT + row * 80 + ch * 16;
        asm volatile("cp.async.cg.shared.global [%0], [%1], 16;" :: "r"(sa), "l"(g));
    }
    asm volatile("cp.async.commit_group;");

    int warpM = wid >> 2, warpN = wid & 3;
    for (int s = 0; s < NSt; s++) {
        int buf = s & 1;
        asm volatile("cp.async.wait_group 0;");
        __syncthreads();
        if (s + 1 < NSt) {
            int kk = (s + 1) << 5;
            for (int u = tid; u < 1024; u += 256) {
                int tile = u >> 9, v = u & 511, row = v >> 2, ch = v & 3;
                const __half* g = (tile ? S + (size_t)(n0 + row) * Kc
                                        : Wh + (size_t)(m0 + row) * Kc) + kk + ch * 8;
                unsigned sa = sb + (unsigned)(tile * 2 + (buf ^ 1)) * TSLOT + row * 80 + ch * 16;
                asm volatile("cp.async.cg.shared.global [%0], [%1], 16;" :: "r"(sa), "l"(g));
            }
            asm volatile("cp.async.commit_group;");
        }
        unsigned bW = sb + (unsigned)buf * TSLOT;
        unsigned bS = sb + (unsigned)(2 + buf) * TSLOT;
#pragma unroll
        for (int ks = 0; ks < 2; ks++) {
            unsigned kb = ks * 32;
            unsigned bf[4][2];
            unsigned bo = (unsigned)(warpN * 32 + (lane & 7)) * 80 + kb + (((lane >> 3) & 1) * 16);
#pragma unroll
            for (int ni = 0; ni < 4; ni++) ldsm2(bf[ni], bS + bo + ni * (8 * 80));
            unsigned ao = (unsigned)(warpM * 64 + (lane & 15)) * 80 + kb + ((lane >> 4) * 16);
            unsigned a[4][4];
#pragma unroll
            for (int mi = 0; mi < 4; mi++) ldsm4(a[mi], bW + ao + mi * (16 * 80));
#pragma unroll
            for (int mi = 0; mi < 4; mi++)
#pragma unroll
                for (int ni = 0; ni < 4; ni++) mmaf16(acc[mi][ni], a[mi], bf[ni]);
        }
        __syncthreads();
    }

    // epilogue
    int g = lane >> 2, cp2 = (lane & 3) * 2;
    int bimg = n0 >> 10;
    int pix0 = (n0 & 1023) + warpN * 32 + cp2;
#pragma unroll
    for (int mi = 0; mi < 4; mi++) {
#pragma unroll
        for (int h8 = 0; h8 < 2; h8++) {
            int row = m0 + warpM * 64 + mi * 16 + g + h8 * 8;
            if (mode == 0 && row >= 256) {
                int r2 = row - 256;
                if (r2 < 50) {
                    float bias = boff[r2];
                    float* dst = offp + ((size_t)bimg * 50 + r2) * 1024;
#pragma unroll
                    for (int ni = 0; ni < 4; ni++) {
                        float2 v;
                        v.x = acc[mi][ni][h8 * 2 + 0] + bias;
                        v.y = acc[mi][ni][h8 * 2 + 1] + bias;
                        *(float2*)(dst + pix0 + ni * 8) = v;
                    }
                }
            } else {
                float sc = scale[row], sh = shift[row];
                size_t base = ((size_t)bimg * 256 + row) * 1024;
#pragma unroll
                for (int ni = 0; ni < 4; ni++) {
                    float2 v;
                    v.x = fmaf(acc[mi][ni][h8 * 2 + 0], sc, sh);
                    v.y = fmaf(acc[mi][ni][h8 * 2 + 1], sc, sh);
                    size_t o = base + pix0 + ni * 8;
                    if (mode == 0) {
                        v.x = fmaxf(v.x, 0.f); v.y = fmaxf(v.y, 0.f);
                    } else if (mode == 2) {
                        float2 a = *(const float2*)(aux + o);
                        v.x = fmaxf(v.x, 0.f) + a.x; v.y = fmaxf(v.y, 0.f) + a.y;
                    } else {
                        float2 a = *(const float2*)(aux + o);
                        v.x = fmaxf(v.x + a.x, 0.f); v.y = fmaxf(v.y + a.y, 0.f);
                    }
                    *(float2*)(outp + o) = v;
                }
            }
        }
    }
}

// ---------------- launcher ----------------
extern "C" void kernel_launch(void* const* d_in, const int* in_sizes, int n_in,
                              void* d_out, int out_size) {
    const float* x     = (const float*)d_in[0];
    const float* w1    = (const float*)d_in[1];
    const float* w_off = (const float*)d_in[2];
    const float* b_off = (const float*)d_in[3];
    const float* w3    = (const float*)d_in[4];
    const float* w2    = (const float*)d_in[5];
    const float* g1 = (const float*)d_in[6],  *b1 = (const float*)d_in[7];
    const float* m1 = (const float*)d_in[8],  *v1 = (const float*)d_in[9];
    const float* g3 = (const float*)d_in[10], *b3 = (const float*)d_in[11];
    const float* m3 = (const float*)d_in[12], *v3 = (const float*)d_in[13];
    const float* g2 = (const float*)d_in[14], *b2 = (const float*)d_in[15];
    const float* m2 = (const float*)d_in[16], *v2 = (const float*)d_in[17];
    float* out = (float*)d_out;

    cudaFuncSetAttribute(gemm_tc, cudaFuncAttributeMaxDynamicSharedMemorySize, GSMEM);

    __half *S, *xTh, *wch, *w3h, *w2h;
    float *gout, *goff, *bn;
    cudaGetSymbolAddress((void**)&S,    g_S);
    cudaGetSymbolAddress((void**)&xTh,  g_xTh);
    cudaGetSymbolAddress((void**)&gout, g_out);
    cudaGetSymbolAddress((void**)&goff, g_offb);
    cudaGetSymbolAddress((void**)&wch, g_wch);
    cudaGetSymbolAddress((void**)&w3h, g_w3h);
    cudaGetSymbolAddress((void**)&w2h, g_w2h);
    cudaGetSymbolAddress((void**)&bn,  g_bn);

    prep_bn<<<1, 256>>>(g1, b1, m1, v1, g3, b3, m3, v3, g2, b2, m2, v2);
    reorder_w_f16<<<2304, 256>>>(w1, wch, 256, 9, 0);
    reorder_w_f16<<<1152, 256>>>(w_off, wch, 50, 9, 256);
    reorder_w_f16<<<6400, 256>>>(w3, w3h, 256, 25, 0);
    reorder_w_f16<<<2304, 256>>>(w2, w2h, 256, 9, 0);

    transpose_cl<<<dim3(32, 8, 32), dim3(32, 8)>>>(x, xTh);
    im2col_h<<<36864, 256>>>(xTh, S);

    // fused conv1 + offset conv (M=384)
    gemm_tc<<<dim3(3, 256), 256, GSMEM>>>(wch, S, KCA, 0,
                                          bn, bn + 256, b_off, nullptr, gout, goff);
    // deformable sampling -> S
    sampler_f16<<<102400, 256>>>(xTh, goff, S);
    // deform conv: gout += relu(bn3)
    gemm_tc<<<dim3(2, 256), 256, GSMEM>>>(w3h, S, KCB, 2,
                                          bn + 512, bn + 768, nullptr, gout, gout, nullptr);

    transpose_cl<<<dim3(32, 8, 32), dim3(32, 8)>>>(gout, xTh);
    im2col_h<<<36864, 256>>>(xTh, S);
    // conv2: relu(bn2 + x) -> out
    gemm_tc<<<dim3(2, 256), 256, GSMEM>>>(w2h, S, KCA, 3,
                                          bn + 1024, bn + 1280, nullptr, x, out, nullptr);
}

// round 15
// speedup vs baseline: 2.2170x; 1.0007x over previous
#include <cuda_runtime.h>
#include <cuda_fp16.h>
#include <math.h>

#define BATCH 32
#define HW    1024
#define NTOT  32768
#define KCA   2304            // 9*256
#define KCB   6400            // 25*256

// ---------------- scratch ----------------
__device__ __half g_SA[(size_t)NTOT * KCA];           // 3x3 im2col plane
__device__ __half g_SB[(size_t)NTOT * KCB];           // deform-sampled plane
__device__ __half g_xTh[(size_t)BATCH * HW * 256];    // NHWC fp16 activations
__device__ float g_out[(size_t)BATCH * 256 * HW];     // conv1 result (NCHW fp32)
__device__ float g_offb[(size_t)BATCH * 50 * HW];
__device__ __half g_wch[(size_t)384 * KCA];
__device__ __half g_w3h[(size_t)256 * KCB];
__device__ __half g_w2h[(size_t)256 * KCA];
__device__ float g_bn[6 * 256];

// ---------------- helpers ----------------
__device__ __forceinline__ unsigned s2u(const void* p) {
    unsigned a;
    asm("{ .reg .u64 t; cvta.to.shared.u64 t, %1; cvt.u32.u64 %0, t; }" : "=r"(a) : "l"(p));
    return a;
}
__device__ __forceinline__ uint4 pack8h(const float* v) {
    unsigned r[4];
#pragma unroll
    for (int i = 0; i < 4; i++) {
        __half2 hp = __floats2half2_rn(v[2 * i], v[2 * i + 1]);
        r[i] = *(unsigned*)&hp;
    }
    return make_uint4(r[0], r[1], r[2], r[3]);
}

// ---------------- prep kernels ----------------
__global__ void prep_bn(const float* g1, const float* b1, const float* m1, const float* v1,
                        const float* g3, const float* b3, const float* m3, const float* v3,
                        const float* g2, const float* b2, const float* m2, const float* v2) {
    int i = threadIdx.x;
    float s1 = g1[i] * rsqrtf(v1[i] + 1e-5f);
    g_bn[i] = s1;          g_bn[256 + i] = b1[i] - m1[i] * s1;
    float s3 = g3[i] * rsqrtf(v3[i] + 1e-5f);
    g_bn[512 + i] = s3;    g_bn[768 + i] = b3[i] - m3[i] * s3;
    float s2 = g2[i] * rsqrtf(v2[i] + 1e-5f);
    g_bn[1024 + i] = s2;   g_bn[1280 + i] = b2[i] - m2[i] * s2;
}

__global__ void reorder_w_f16(const float* __restrict__ w, __half* __restrict__ Wh,
                              int Ov, int T, int rowoff) {
    int idx = blockIdx.x * 256 + threadIdx.x;
    int c = idx & 255;
    int t = (idx >> 8) % T;
    int o = idx / (256 * T);
    float v = (o < Ov) ? w[((size_t)(o * 256 + c)) * T + t] : 0.f;
    Wh[(size_t)(rowoff + o) * (T * 256) + t * 256 + c] = __float2half_rn(v);
}

// NCHW fp32 -> NHWC fp16
__global__ void transpose_cl(const float* __restrict__ in, __half* __restrict__ out) {
    __shared__ float tile[32][33];
    int b = blockIdx.z, c0 = blockIdx.y * 32, p0 = blockIdx.x * 32;
    int tx = threadIdx.x, ty = threadIdx.y;
    const float* ib = in + ((size_t)b << 18);
#pragma unroll
    for (int i = 0; i < 32; i += 8)
        tile[ty + i][tx] = ib[(size_t)(c0 + ty + i) * 1024 + p0 + tx];
    __syncthreads();
    __half* ob = out + ((size_t)b << 18);
#pragma unroll
    for (int i = 0; i < 32; i += 8)
        ob[(size_t)(p0 + ty + i) * 256 + c0 + tx] = __float2half_rn(tile[tx][ty + i]);
}

// im2col 3x3 pad1: xTh (NHWC fp16) -> S[n][k] — pure 16B gather-copy
__global__ void im2col_h(const __half* __restrict__ xT, __half* __restrict__ S) {
    int idx = blockIdx.x * 256 + threadIdx.x;     // NTOT*9*32
    int c8 = idx & 31;
    int t  = (idx >> 5) % 9;
    int n  = idx / 288;
    int p = n & 1023, b = n >> 10;
    int y = (p >> 5) - 1 + t / 3;
    int x = (p & 31) - 1 + t % 3;
    uint4 v = make_uint4(0, 0, 0, 0);
    if ((unsigned)y < 32u && (unsigned)x < 32u)
        v = *(const uint4*)(xT + ((size_t)b << 18) + (size_t)(y * 32 + x) * 256 + c8 * 8);
    *(uint4*)(S + (size_t)n * KCA + t * 256 + c8 * 8) = v;
}

// deformable bilinear sampler: xTh (NHWC fp16) -> S[n][k] fp16
__global__ void sampler_f16(const __half* __restrict__ xT, const float* __restrict__ off,
                            __half* __restrict__ S) {
    int idx = blockIdx.x * 256 + threadIdx.x;     // NTOT*25*32
    int c8 = idx & 31;
    int k  = (idx >> 5) % 25;
    int n  = idx / 800;
    int p = n & 1023, b = n >> 10;
    int ho = p >> 5, wo = p & 31;
    const float* ob = off + (size_t)b * (50 * 1024);
    float dy = ob[(2 * k) * 1024 + p];
    float dx = ob[(2 * k + 1) * 1024 + p];
    float py = (float)(ho - 2 + k / 5) + dy;
    float px = (float)(wo - 2 + k % 5) + dx;
    float y0f = floorf(py), x0f = floorf(px);
    float wy1 = py - y0f, wx1 = px - x0f;
    float wy0 = 1.f - wy1, wx0 = 1.f - wx1;
    int y0 = (int)y0f, x0 = (int)x0f, y1 = y0 + 1, x1 = x0 + 1;
    float w00 = ((unsigned)y0 < 32u && (unsigned)x0 < 32u) ? wy0 * wx0 : 0.f;
    float w01 = ((unsigned)y0 < 32u && (unsigned)x1 < 32u) ? wy0 * wx1 : 0.f;
    float w10 = ((unsigned)y1 < 32u && (unsigned)x0 < 32u) ? wy1 * wx0 : 0.f;
    float w11 = ((unsigned)y1 < 32u && (unsigned)x1 < 32u) ? wy1 * wx1 : 0.f;
    int cy0 = min(max(y0, 0), 31), cy1 = min(max(y1, 0), 31);
    int cx0 = min(max(x0, 0), 31), cx1 = min(max(x1, 0), 31);
    const __half* xb = xT + ((size_t)b << 18);
    uint4 u00 = *(const uint4*)(xb + (size_t)(cy0 * 32 + cx0) * 256 + c8 * 8);
    uint4 u01 = *(const uint4*)(xb + (size_t)(cy0 * 32 + cx1) * 256 + c8 * 8);
    uint4 u10 = *(const uint4*)(xb + (size_t)(cy1 * 32 + cx0) * 256 + c8 * 8);
    uint4 u11 = *(const uint4*)(xb + (size_t)(cy1 * 32 + cx1) * 256 + c8 * 8);
    const __half2* h00 = (const __half2*)&u00;
    const __half2* h01 = (const __half2*)&u01;
    const __half2* h10 = (const __half2*)&u10;
    const __half2* h11 = (const __half2*)&u11;
    float vs[8];
#pragma unroll
    for (int q = 0; q < 4; q++) {
        float2 a = __half22float2(h00[q]), c = __half22float2(h01[q]);
        float2 d = __half22float2(h10[q]), e = __half22float2(h11[q]);
        vs[q*2+0] = w00*a.x + w01*c.x + w10*d.x + w11*e.x;
        vs[q*2+1] = w00*a.y + w01*c.y + w10*d.y + w11*e.y;
    }
    *(uint4*)(S + (size_t)n * KCB + k * 256 + c8 * 8) = pack8h(vs);
}

// ---------------- mma.sync GEMM: C = Wh · S, fused epilogue -----------------
// mode 0: rows<256 relu(bn)->outp(fp32 NCHW); rows>=256 +boff->offp
// mode 2: outh(NHWC fp16) = aux(fp32 NCHW) + relu(bn(C))
// mode 3: outp = relu(bn(C) + aux)
#define TSLOT 10240                    // 128 rows * 80 bytes
#define GSMEM (4 * TSLOT)

__device__ __forceinline__ void ldsm4(unsigned* r, unsigned a) {
    asm volatile("ldmatrix.sync.aligned.m8n8.x4.shared.b16 {%0,%1,%2,%3}, [%4];"
                 : "=r"(r[0]), "=r"(r[1]), "=r"(r[2]), "=r"(r[3]) : "r"(a));
}
__device__ __forceinline__ void ldsm2(unsigned* r, unsigned a) {
    asm volatile("ldmatrix.sync.aligned.m8n8.x2.shared.b16 {%0,%1}, [%2];"
                 : "=r"(r[0]), "=r"(r[1]) : "r"(a));
}
__device__ __forceinline__ void mmaf16(float* d, const unsigned* a, const unsigned* b) {
    asm volatile("mma.sync.aligned.m16n8k16.row.col.f32.f16.f16.f32 "
                 "{%0,%1,%2,%3}, {%4,%5,%6,%7}, {%8,%9}, {%0,%1,%2,%3};"
                 : "+f"(d[0]), "+f"(d[1]), "+f"(d[2]), "+f"(d[3])
                 : "r"(a[0]), "r"(a[1]), "r"(a[2]), "r"(a[3]), "r"(b[0]), "r"(b[1]));
}

__global__ __launch_bounds__(256, 2) void gemm_tc(
    const __half* __restrict__ Wh, const __half* __restrict__ S,
    int Kc, int mbase, int mode,
    const float* __restrict__ scale, const float* __restrict__ shift,
    const float* __restrict__ boff, const float* __restrict__ aux,
    float* __restrict__ outp, __half* __restrict__ outh, float* __restrict__ offp)
{
    extern __shared__ char sm[];
    unsigned sb = s2u(sm);
    int tid = threadIdx.x, wid = tid >> 5, lane = tid & 31;
    int m0 = blockIdx.x * 128 + mbase;
    int n0 = blockIdx.y * 128;

    float acc[4][4][4];
#pragma unroll
    for (int i = 0; i < 4; i++)
#pragma unroll
        for (int j = 0; j < 4; j++) {
            acc[i][j][0] = 0.f; acc[i][j][1] = 0.f; acc[i][j][2] = 0.f; acc[i][j][3] = 0.f;
        }

    int NSt = Kc >> 5;

    // prologue: stage 0 -> buf 0 (tiles: 0 = W, 1 = S)
    for (int u = tid; u < 1024; u += 256) {
        int tile = u >> 9, v = u & 511, row = v >> 2, ch = v & 3;
        const __half* g = (tile ? S + (size_t)(n0 + row) * Kc
                                : Wh + (size_t)(m0 + row) * Kc) + ch * 8;
        unsigned sa = sb + (unsigned)(tile * 2) * TSLOT + row * 80 + ch * 16;
        asm volatile("cp.async.cg.shared.global [%0], [%1], 16;" :: "r"(sa), "l"(g));
    }
    asm volatile("cp.async.commit_group;");

    int warpM = wid >> 2, warpN = wid & 3;
    for (int s = 0; s < NSt; s++) {
        int buf = s & 1;
        asm volatile("cp.async.wait_group 0;");
        __syncthreads();
        if (s + 1 < NSt) {
            int kk = (s + 1) << 5;
            for (int u = tid; u < 1024; u += 256) {
                int tile = u >> 9, v = u & 511, row = v >> 2, ch = v & 3;
                const __half* g = (tile ? S + (size_t)(n0 + row) * Kc
                                        : Wh + (size_t)(m0 + row) * Kc) + kk + ch * 8;
                unsigned sa = sb + (unsigned)(tile * 2 + (buf ^ 1)) * TSLOT + row * 80 + ch * 16;
                asm volatile("cp.async.cg.shared.global [%0], [%1], 16;" :: "r"(sa), "l"(g));
            }
            asm volatile("cp.async.commit_group;");
        }
        unsigned bW = sb + (unsigned)buf * TSLOT;
        unsigned bS = sb + (unsigned)(2 + buf) * TSLOT;
#pragma unroll
        for (int ks = 0; ks < 2; ks++) {
            unsigned kb = ks * 32;
            unsigned bf[4][2];
            unsigned bo = (unsigned)(warpN * 32 + (lane & 7)) * 80 + kb + (((lane >> 3) & 1) * 16);
#pragma unroll
            for (int ni = 0; ni < 4; ni++) ldsm2(bf[ni], bS + bo + ni * (8 * 80));
            unsigned ao = (unsigned)(warpM * 64 + (lane & 15)) * 80 + kb + ((lane >> 4) * 16);
            unsigned a[4][4];
#pragma unroll
            for (int mi = 0; mi < 4; mi++) ldsm4(a[mi], bW + ao + mi * (16 * 80));
#pragma unroll
            for (int mi = 0; mi < 4; mi++)
#pragma unroll
                for (int ni = 0; ni < 4; ni++) mmaf16(acc[mi][ni], a[mi], bf[ni]);
        }
        __syncthreads();
    }

    // epilogue
    int g = lane >> 2, cp2 = (lane & 3) * 2;
    int bimg = n0 >> 10;
    int pix0 = (n0 & 1023) + warpN * 32 + cp2;
#pragma unroll
    for (int mi = 0; mi < 4; mi++) {
#pragma unroll
        for (int h8 = 0; h8 < 2; h8++) {
            int row = m0 + warpM * 64 + mi * 16 + g + h8 * 8;
            if (mode == 0 && row >= 256) {
                int r2 = row - 256;
                if (r2 < 50) {
                    float bias = boff[r2];
                    float* dst = offp + ((size_t)bimg * 50 + r2) * 1024;
#pragma unroll
                    for (int ni = 0; ni < 4; ni++) {
                        float2 v;
                        v.x = acc[mi][ni][h8 * 2 + 0] + bias;
                        v.y = acc[mi][ni][h8 * 2 + 1] + bias;
                        *(float2*)(dst + pix0 + ni * 8) = v;
                    }
                }
            } else {
                float sc = scale[row], sh = shift[row];
                size_t base = ((size_t)bimg * 256 + row) * 1024;
#pragma unroll
                for (int ni = 0; ni < 4; ni++) {
                    float vx = fmaf(acc[mi][ni][h8 * 2 + 0], sc, sh);
                    float vy = fmaf(acc[mi][ni][h8 * 2 + 1], sc, sh);
                    size_t o = base + pix0 + ni * 8;
                    if (mode == 0) {
                        float2 v; v.x = fmaxf(vx, 0.f); v.y = fmaxf(vy, 0.f);
                        *(float2*)(outp + o) = v;
                    } else if (mode == 2) {
                        float2 a = *(const float2*)(aux + o);
                        float rx = fmaxf(vx, 0.f) + a.x;
                        float ry = fmaxf(vy, 0.f) + a.y;
                        __half* dh = outh + ((size_t)bimg << 18);
                        int pix = pix0 + ni * 8;
                        dh[(size_t)pix * 256 + row]       = __float2half_rn(rx);
                        dh[(size_t)(pix + 1) * 256 + row] = __float2half_rn(ry);
                    } else {
                        float2 a = *(const float2*)(aux + o);
                        float2 v;
                        v.x = fmaxf(vx + a.x, 0.f); v.y = fmaxf(vy + a.y, 0.f);
                        *(float2*)(outp + o) = v;
                    }
                }
            }
        }
    }
}

// ---------------- launcher ----------------
extern "C" void kernel_launch(void* const* d_in, const int* in_sizes, int n_in,
                              void* d_out, int out_size) {
    const float* x     = (const float*)d_in[0];
    const float* w1    = (const float*)d_in[1];
    const float* w_off = (const float*)d_in[2];
    const float* b_off = (const float*)d_in[3];
    const float* w3    = (const float*)d_in[4];
    const float* w2    = (const float*)d_in[5];
    const float* g1 = (const float*)d_in[6],  *b1 = (const float*)d_in[7];
    const float* m1 = (const float*)d_in[8],  *v1 = (const float*)d_in[9];
    const float* g3 = (const float*)d_in[10], *b3 = (const float*)d_in[11];
    const float* m3 = (const float*)d_in[12], *v3 = (const float*)d_in[13];
    const float* g2 = (const float*)d_in[14], *b2 = (const float*)d_in[15];
    const float* m2 = (const float*)d_in[16], *v2 = (const float*)d_in[17];
    float* out = (float*)d_out;

    cudaFuncSetAttribute(gemm_tc, cudaFuncAttributeMaxDynamicSharedMemorySize, GSMEM);

    // streams/events created once, pre-capture (first call is the correctness run)
    static cudaStream_t s_aux = nullptr;
    static cudaEvent_t ev0 = nullptr, evA = nullptr, evB = nullptr, evC = nullptr;
    if (!s_aux) {
        cudaStreamCreateWithFlags(&s_aux, cudaStreamNonBlocking);
        cudaEventCreateWithFlags(&ev0, cudaEventDisableTiming);
        cudaEventCreateWithFlags(&evA, cudaEventDisableTiming);
        cudaEventCreateWithFlags(&evB, cudaEventDisableTiming);
        cudaEventCreateWithFlags(&evC, cudaEventDisableTiming);
    }

    __half *SA, *SB, *xTh, *wch, *w3h, *w2h;
    float *gout, *goff, *bn;
    cudaGetSymbolAddress((void**)&SA,   g_SA);
    cudaGetSymbolAddress((void**)&SB,   g_SB);
    cudaGetSymbolAddress((void**)&xTh,  g_xTh);
    cudaGetSymbolAddress((void**)&gout, g_out);
    cudaGetSymbolAddress((void**)&goff, g_offb);
    cudaGetSymbolAddress((void**)&wch, g_wch);
    cudaGetSymbolAddress((void**)&w3h, g_w3h);
    cudaGetSymbolAddress((void**)&w2h, g_w2h);
    cudaGetSymbolAddress((void**)&bn,  g_bn);

    // fork: weight prep on s_aux, activation prep on stream 0
    cudaEventRecord(ev0, 0);
    cudaStreamWaitEvent(s_aux, ev0, 0);
    prep_bn<<<1, 256, 0, s_aux>>>(g1, b1, m1, v1, g3, b3, m3, v3, g2, b2, m2, v2);
    reorder_w_f16<<<2304, 256, 0, s_aux>>>(w1, wch, 256, 9, 0);
    reorder_w_f16<<<1152, 256, 0, s_aux>>>(w_off, wch, 50, 9, 256);
    reorder_w_f16<<<6400, 256, 0, s_aux>>>(w3, w3h, 256, 25, 0);
    reorder_w_f16<<<2304, 256, 0, s_aux>>>(w2, w2h, 256, 9, 0);
    cudaEventRecord(evA, s_aux);

    transpose_cl<<<dim3(32, 8, 32), dim3(32, 8)>>>(x, xTh);
    im2col_h<<<36864, 256>>>(xTh, SA);
    cudaStreamWaitEvent(0, evA, 0);

    // offset conv first (M rows 256..383 of wch) -> goff
    gemm_tc<<<dim3(1, 256), 256, GSMEM>>>(wch, SA, KCA, 256, 0,
                                          bn, bn + 256, b_off, nullptr,
                                          gout, nullptr, goff);
    // fork: conv1 GEMM on s_aux concurrent with sampler on stream 0
    cudaEventRecord(evB, 0);
    cudaStreamWaitEvent(s_aux, evB, 0);
    gemm_tc<<<dim3(2, 256), 256, GSMEM, s_aux>>>(wch, SA, KCA, 0, 0,
                                                 bn, bn + 256, b_off, nullptr,
                                                 gout, nullptr, goff);
    cudaEventRecord(evC, s_aux);

    sampler_f16<<<102400, 256>>>(xTh, goff, SB);
    cudaStreamWaitEvent(0, evC, 0);

    // deform conv: xTh(NHWC fp16) = gout + relu(bn3(C))
    gemm_tc<<<dim3(2, 256), 256, GSMEM>>>(w3h, SB, KCB, 0, 2,
                                          bn + 512, bn + 768, nullptr, gout,
                                          nullptr, xTh, nullptr);
    im2col_h<<<36864, 256>>>(xTh, SA);
    // conv2: relu(bn2(C) + x) -> out
    gemm_tc<<<dim3(2, 256), 256, GSMEM>>>(w2h, SA, KCA, 0, 3,
                                          bn + 1024, bn + 1280, nullptr, x,
                                          out, nullptr, nullptr);
}

// round 17
// speedup vs baseline: 2.4848x; 1.1208x over previous
#include <cuda_runtime.h>
#include <cuda_fp16.h>
#include <math.h>

#define BATCH 32
#define HW    1024
#define NTOT  32768
#define KCA   2304            // 9*256
#define KCB   6400            // 25*256

// ---------------- scratch ----------------
__device__ __half g_SB[(size_t)NTOT * KCB];           // deform-sampled plane
__device__ __half g_xTh[(size_t)BATCH * HW * 256];    // NHWC fp16 activations
__device__ float g_out[(size_t)BATCH * 256 * HW];     // conv1 result (NCHW fp32)
__device__ float g_offb[(size_t)BATCH * 50 * HW];
__device__ __half g_wch[(size_t)384 * KCA];
__device__ __half g_w3h[(size_t)256 * KCB];
__device__ __half g_w2h[(size_t)256 * KCA];
__device__ float g_bn[6 * 256];

// ---------------- helpers ----------------
__device__ __forceinline__ unsigned s2u(const void* p) {
    unsigned a;
    asm("{ .reg .u64 t; cvta.to.shared.u64 t, %1; cvt.u32.u64 %0, t; }" : "=r"(a) : "l"(p));
    return a;
}
__device__ __forceinline__ uint4 pack8h(const float* v) {
    unsigned r[4];
#pragma unroll
    for (int i = 0; i < 4; i++) {
        __half2 hp = __floats2half2_rn(v[2 * i], v[2 * i + 1]);
        r[i] = *(unsigned*)&hp;
    }
    return make_uint4(r[0], r[1], r[2], r[3]);
}

// ---------------- prep kernels ----------------
__global__ void prep_bn(const float* g1, const float* b1, const float* m1, const float* v1,
                        const float* g3, const float* b3, const float* m3, const float* v3,
                        const float* g2, const float* b2, const float* m2, const float* v2) {
    int i = threadIdx.x;
    float s1 = g1[i] * rsqrtf(v1[i] + 1e-5f);
    g_bn[i] = s1;          g_bn[256 + i] = b1[i] - m1[i] * s1;
    float s3 = g3[i] * rsqrtf(v3[i] + 1e-5f);
    g_bn[512 + i] = s3;    g_bn[768 + i] = b3[i] - m3[i] * s3;
    float s2 = g2[i] * rsqrtf(v2[i] + 1e-5f);
    g_bn[1024 + i] = s2;   g_bn[1280 + i] = b2[i] - m2[i] * s2;
}

__global__ void reorder_w_f16(const float* __restrict__ w, __half* __restrict__ Wh,
                              int Ov, int T, int rowoff) {
    int idx = blockIdx.x * 256 + threadIdx.x;
    int c = idx & 255;
    int t = (idx >> 8) % T;
    int o = idx / (256 * T);
    float v = (o < Ov) ? w[((size_t)(o * 256 + c)) * T + t] : 0.f;
    Wh[(size_t)(rowoff + o) * (T * 256) + t * 256 + c] = __float2half_rn(v);
}

// NCHW fp32 -> NHWC fp16
__global__ void transpose_cl(const float* __restrict__ in, __half* __restrict__ out) {
    __shared__ float tile[32][33];
    int b = blockIdx.z, c0 = blockIdx.y * 32, p0 = blockIdx.x * 32;
    int tx = threadIdx.x, ty = threadIdx.y;
    const float* ib = in + ((size_t)b << 18);
#pragma unroll
    for (int i = 0; i < 32; i += 8)
        tile[ty + i][tx] = ib[(size_t)(c0 + ty + i) * 1024 + p0 + tx];
    __syncthreads();
    __half* ob = out + ((size_t)b << 18);
#pragma unroll
    for (int i = 0; i < 32; i += 8)
        ob[(size_t)(p0 + ty + i) * 256 + c0 + tx] = __float2half_rn(tile[tx][ty + i]);
}

// deformable bilinear sampler: xTh (NHWC fp16) -> S[n][k] fp16
__global__ void sampler_f16(const __half* __restrict__ xT, const float* __restrict__ off,
                            __half* __restrict__ S) {
    int idx = blockIdx.x * 256 + threadIdx.x;     // NTOT*25*32
    int c8 = idx & 31;
    int k  = (idx >> 5) % 25;
    int n  = idx / 800;
    int p = n & 1023, b = n >> 10;
    int ho = p >> 5, wo = p & 31;
    const float* ob = off + (size_t)b * (50 * 1024);
    float dy = ob[(2 * k) * 1024 + p];
    float dx = ob[(2 * k + 1) * 1024 + p];
    float py = (float)(ho - 2 + k / 5) + dy;
    float px = (float)(wo - 2 + k % 5) + dx;
    float y0f = floorf(py), x0f = floorf(px);
    float wy1 = py - y0f, wx1 = px - x0f;
    float wy0 = 1.f - wy1, wx0 = 1.f - wx1;
    int y0 = (int)y0f, x0 = (int)x0f, y1 = y0 + 1, x1 = x0 + 1;
    float w00 = ((unsigned)y0 < 32u && (unsigned)x0 < 32u) ? wy0 * wx0 : 0.f;
    float w01 = ((unsigned)y0 < 32u && (unsigned)x1 < 32u) ? wy0 * wx1 : 0.f;
    float w10 = ((unsigned)y1 < 32u && (unsigned)x0 < 32u) ? wy1 * wx0 : 0.f;
    float w11 = ((unsigned)y1 < 32u && (unsigned)x1 < 32u) ? wy1 * wx1 : 0.f;
    int cy0 = min(max(y0, 0), 31), cy1 = min(max(y1, 0), 31);
    int cx0 = min(max(x0, 0), 31), cx1 = min(max(x1, 0), 31);
    const __half* xb = xT + ((size_t)b << 18);
    uint4 u00 = *(const uint4*)(xb + (size_t)(cy0 * 32 + cx0) * 256 + c8 * 8);
    uint4 u01 = *(const uint4*)(xb + (size_t)(cy0 * 32 + cx1) * 256 + c8 * 8);
    uint4 u10 = *(const uint4*)(xb + (size_t)(cy1 * 32 + cx0) * 256 + c8 * 8);
    uint4 u11 = *(const uint4*)(xb + (size_t)(cy1 * 32 + cx1) * 256 + c8 * 8);
    const __half2* h00 = (const __half2*)&u00;
    const __half2* h01 = (const __half2*)&u01;
    const __half2* h10 = (const __half2*)&u10;
    const __half2* h11 = (const __half2*)&u11;
    float vs[8];
#pragma unroll
    for (int q = 0; q < 4; q++) {
        float2 a = __half22float2(h00[q]), c = __half22float2(h01[q]);
        float2 d = __half22float2(h10[q]), e = __half22float2(h11[q]);
        vs[q*2+0] = w00*a.x + w01*c.x + w10*d.x + w11*e.x;
        vs[q*2+1] = w00*a.y + w01*c.y + w10*d.y + w11*e.y;
    }
    *(uint4*)(S + (size_t)n * KCB + k * 256 + c8 * 8) = pack8h(vs);
}

// ---------------- mma.sync GEMM: C = Wh · B, fused epilogue -----------------
// imp=1: B = implicit 3x3/pad1 taps from NHWC fp16 plane (Bsrc=xTh), Kc=2304
// imp=0: B = materialized rows (Bsrc=S_B), stride Kc
// mode 0: rows<256 relu(bn)->outp(fp32 NCHW); rows>=256 +boff->offp
// mode 2: outh(NHWC fp16, smem-staged) = aux(fp32 NCHW) + relu(bn(C))
// mode 3: outp = relu(bn(C) + aux)
#define TSLOT 10240                    // 128 rows * 80 bytes
#define GSMEM (4 * TSLOT)

__device__ __forceinline__ void ldsm4(unsigned* r, unsigned a) {
    asm volatile("ldmatrix.sync.aligned.m8n8.x4.shared.b16 {%0,%1,%2,%3}, [%4];"
                 : "=r"(r[0]), "=r"(r[1]), "=r"(r[2]), "=r"(r[3]) : "r"(a));
}
__device__ __forceinline__ void ldsm2(unsigned* r, unsigned a) {
    asm volatile("ldmatrix.sync.aligned.m8n8.x2.shared.b16 {%0,%1}, [%2];"
                 : "=r"(r[0]), "=r"(r[1]) : "r"(a));
}
__device__ __forceinline__ void mmaf16(float* d, const unsigned* a, const unsigned* b) {
    asm volatile("mma.sync.aligned.m16n8k16.row.col.f32.f16.f16.f32 "
                 "{%0,%1,%2,%3}, {%4,%5,%6,%7}, {%8,%9}, {%0,%1,%2,%3};"
                 : "+f"(d[0]), "+f"(d[1]), "+f"(d[2]), "+f"(d[3])
                 : "r"(a[0]), "r"(a[1]), "r"(a[2]), "r"(a[3]), "r"(b[0]), "r"(b[1]));
}
__device__ __forceinline__ void cpa16(unsigned sa, const void* g) {
    asm volatile("cp.async.cg.shared.global [%0], [%1], 16;" :: "r"(sa), "l"(g));
}
__device__ __forceinline__ void cpa16z(unsigned sa, const void* g, int sz) {
    asm volatile("cp.async.cg.shared.global [%0], [%1], 16, %2;" :: "r"(sa), "l"(g), "r"(sz));
}

__global__ __launch_bounds__(256, 2) void gemm_tc(
    const __half* __restrict__ Wh, const __half* __restrict__ Bsrc,
    int Kc, int imp, int mbase, int mode,
    const float* __restrict__ scale, const float* __restrict__ shift,
    const float* __restrict__ boff, const float* __restrict__ aux,
    float* __restrict__ outp, __half* __restrict__ outh, float* __restrict__ offp)
{
    extern __shared__ char sm[];
    unsigned sb = s2u(sm);
    int tid = threadIdx.x, wid = tid >> 5, lane = tid & 31;
    int m0 = blockIdx.x * 128 + mbase;
    int n0 = blockIdx.y * 128;
    int bimg = n0 >> 10;
    int pbase = n0 & 1023;

    // per-thread fixed loader coordinates
    int r1 = tid >> 2;                 // row 0..63
    int ch = tid & 3;                  // 16B chunk 0..3 within 64B k-slab
    int p1 = pbase + r1, p2 = p1 + 64;

    // 9-bit tap-validity masks (imp mode)
    unsigned mk1 = 0, mk2 = 0;
    if (imp) {
#pragma unroll
        for (int t = 0; t < 9; t++) {
            int i = t / 3 - 1, j = t % 3 - 1;
            if ((unsigned)((p1 >> 5) + i) < 32u && (unsigned)((p1 & 31) + j) < 32u) mk1 |= 1u << t;
            if ((unsigned)((p2 >> 5) + i) < 32u && (unsigned)((p2 & 31) + j) < 32u) mk2 |= 1u << t;
        }
    }

    float acc[4][4][4];
#pragma unroll
    for (int i = 0; i < 4; i++)
#pragma unroll
        for (int j = 0; j < 4; j++) {
            acc[i][j][0] = 0.f; acc[i][j][1] = 0.f; acc[i][j][2] = 0.f; acc[i][j][3] = 0.f;
        }

    int NSt = Kc >> 5;

    const __half* xb = Bsrc + (((size_t)bimg) << 18);   // imp: image base

    auto load_stage = [&](int s, int buf) {
        int kk = s << 5;
        // A tile (rows r1, r1+64)
        {
            const __half* gA = Wh + (size_t)(m0 + r1) * Kc + kk + ch * 8;
            unsigned saA = sb + (unsigned)buf * TSLOT + r1 * 80 + ch * 16;
            cpa16(saA, gA);
            cpa16(saA + 64 * 80, gA + (size_t)64 * Kc);
        }
        // B tile
        if (!imp) {
            const __half* gB = Bsrc + (size_t)(n0 + r1) * Kc + kk + ch * 8;
            unsigned saB = sb + (unsigned)(2 + buf) * TSLOT + r1 * 80 + ch * 16;
            cpa16(saB, gB);
            cpa16(saB + 64 * 80, gB + (size_t)64 * Kc);
        } else {
            int t = s >> 3;
            int i3 = (t >= 3) + (t >= 6);
            int di = (i3 - 1) * 32 + (t - i3 * 3 - 1);   // pixel delta
            int c0 = (s & 7) * 32 + ch * 8;              // k within tap
            unsigned saB = sb + (unsigned)(2 + buf) * TSLOT + r1 * 80 + ch * 16;
            int sp1 = min(max(p1 + di, 0), 1023);
            int sp2 = min(max(p2 + di, 0), 1023);
            cpa16z(saB, xb + ((size_t)sp1 << 8) + c0, ((mk1 >> t) & 1) ? 16 : 0);
            cpa16z(saB + 64 * 80, xb + ((size_t)sp2 << 8) + c0, ((mk2 >> t) & 1) ? 16 : 0);
        }
    };

    load_stage(0, 0);
    asm volatile("cp.async.commit_group;");

    int warpM = wid >> 2, warpN = wid & 3;
    for (int s = 0; s < NSt; s++) {
        int buf = s & 1;
        asm volatile("cp.async.wait_group 0;");
        __syncthreads();
        if (s + 1 < NSt) {
            load_stage(s + 1, buf ^ 1);
            asm volatile("cp.async.commit_group;");
        }
        unsigned bW = sb + (unsigned)buf * TSLOT;
        unsigned bS = sb + (unsigned)(2 + buf) * TSLOT;
#pragma unroll
        for (int ks = 0; ks < 2; ks++) {
            unsigned kb = ks * 32;
            unsigned bf[4][2];
            unsigned bo = (unsigned)(warpN * 32 + (lane & 7)) * 80 + kb + (((lane >> 3) & 1) * 16);
#pragma unroll
            for (int ni = 0; ni < 4; ni++) ldsm2(bf[ni], bS + bo + ni * (8 * 80));
            unsigned ao = (unsigned)(warpM * 64 + (lane & 15)) * 80 + kb + ((lane >> 4) * 16);
            unsigned a[4][4];
#pragma unroll
            for (int mi = 0; mi < 4; mi++) ldsm4(a[mi], bW + ao + mi * (16 * 80));
#pragma unroll
            for (int mi = 0; mi < 4; mi++)
#pragma unroll
                for (int ni = 0; ni < 4; ni++) mmaf16(acc[mi][ni], a[mi], bf[ni]);
        }
        __syncthreads();
    }

    // ---------------- epilogue ----------------
    int g = lane >> 2, cp2 = (lane & 3) * 2;
    int pix0 = pbase + warpN * 32 + cp2;

    if (mode == 2) {
        // stage BN+relu+aux result into smem [c_local][pix_local], stride 130
        __half* S2 = (__half*)sm;
#pragma unroll
        for (int mi = 0; mi < 4; mi++) {
#pragma unroll
            for (int h8 = 0; h8 < 2; h8++) {
                int rl = warpM * 64 + mi * 16 + g + h8 * 8;   // c_local
                int row = m0 + rl;
                float sc = scale[row], sh = shift[row];
                size_t base = ((size_t)bimg * 256 + row) * 1024;
#pragma unroll
                for (int ni = 0; ni < 4; ni++) {
                    float vx = fmaf(acc[mi][ni][h8 * 2 + 0], sc, sh);
                    float vy = fmaf(acc[mi][ni][h8 * 2 + 1], sc, sh);
                    size_t o = base + pix0 + ni * 8;
                    float2 a = *(const float2*)(aux + o);
                    __half2 hv = __floats2half2_rn(fmaxf(vx, 0.f) + a.x, fmaxf(vy, 0.f) + a.y);
                    int pl = warpN * 32 + cp2 + ni * 8;       // pix_local (even)
                    *(__half2*)&S2[rl * 130 + pl] = hv;
                }
            }
        }
        __syncthreads();
        // coalesced write: each warp 16 pixel rows, 256B per row
#pragma unroll
        for (int pr = 0; pr < 16; pr++) {
            int pl = wid * 16 + pr;
            int c0 = lane * 4;
            __half v0 = S2[(c0 + 0) * 0 + 0];   // placeholder avoid unused warn
            (void)v0;
            __half hv[4];
#pragma unroll
            for (int q = 0; q < 4; q++) hv[q] = S2[(size_t)(c0 + q) * 130 + pl];
            // wait: layout is S2[c*130+pix]? stored as S2[rl*130+pl] with rl=c → yes [c][pix]
            *(uint2*)&outh[(((size_t)bimg << 10) + pbase + pl) * 256 + m0 + c0] = *(uint2*)hv;
        }
    } else {
#pragma unroll
        for (int mi = 0; mi < 4; mi++) {
#pragma unroll
            for (int h8 = 0; h8 < 2; h8++) {
                int row = m0 + warpM * 64 + mi * 16 + g + h8 * 8;
                if (mode == 0 && row >= 256) {
                    int r2 = row - 256;
                    if (r2 < 50) {
                        float bias = boff[r2];
                        float* dst = offp + ((size_t)bimg * 50 + r2) * 1024;
#pragma unroll
                        for (int ni = 0; ni < 4; ni++) {
                            float2 v;
                            v.x = acc[mi][ni][h8 * 2 + 0] + bias;
                            v.y = acc[mi][ni][h8 * 2 + 1] + bias;
                            *(float2*)(dst + pix0 + ni * 8) = v;
                        }
                    }
                } else {
                    float sc = scale[row], sh = shift[row];
                    size_t base = ((size_t)bimg * 256 + row) * 1024;
#pragma unroll
                    for (int ni = 0; ni < 4; ni++) {
                        float vx = fmaf(acc[mi][ni][h8 * 2 + 0], sc, sh);
                        float vy = fmaf(acc[mi][ni][h8 * 2 + 1], sc, sh);
                        size_t o = base + pix0 + ni * 8;
                        float2 v;
                        if (mode == 0) {
                            v.x = fmaxf(vx, 0.f); v.y = fmaxf(vy, 0.f);
                        } else {
                            float2 a = *(const float2*)(aux + o);
                            v.x = fmaxf(vx + a.x, 0.f); v.y = fmaxf(vy + a.y, 0.f);
                        }
                        *(float2*)(outp + o) = v;
                    }
                }
            }
        }
    }
}

// ---------------- launcher ----------------
extern "C" void kernel_launch(void* const* d_in, const int* in_sizes, int n_in,
                              void* d_out, int out_size) {
    const float* x     = (const float*)d_in[0];
    const float* w1    = (const float*)d_in[1];
    const float* w_off = (const float*)d_in[2];
    const float* b_off = (const float*)d_in[3];
    const float* w3    = (const float*)d_in[4];
    const float* w2    = (const float*)d_in[5];
    const float* g1 = (const float*)d_in[6],  *b1 = (const float*)d_in[7];
    const float* m1 = (const float*)d_in[8],  *v1 = (const float*)d_in[9];
    const float* g3 = (const float*)d_in[10], *b3 = (const float*)d_in[11];
    const float* m3 = (const float*)d_in[12], *v3 = (const float*)d_in[13];
    const float* g2 = (const float*)d_in[14], *b2 = (const float*)d_in[15];
    const float* m2 = (const float*)d_in[16], *v2 = (const float*)d_in[17];
    float* out = (float*)d_out;

    cudaFuncSetAttribute(gemm_tc, cudaFuncAttributeMaxDynamicSharedMemorySize, GSMEM);

    static cudaStream_t s_aux = nullptr;
    static cudaEvent_t ev0 = nullptr, evA = nullptr;
    if (!s_aux) {
        cudaStreamCreateWithFlags(&s_aux, cudaStreamNonBlocking);
        cudaEventCreateWithFlags(&ev0, cudaEventDisableTiming);
        cudaEventCreateWithFlags(&evA, cudaEventDisableTiming);
    }

    __half *SB, *xTh, *wch, *w3h, *w2h;
    float *gout, *goff, *bn;
    cudaGetSymbolAddress((void**)&SB,   g_SB);
    cudaGetSymbolAddress((void**)&xTh,  g_xTh);
    cudaGetSymbolAddress((void**)&gout, g_out);
    cudaGetSymbolAddress((void**)&goff, g_offb);
    cudaGetSymbolAddress((void**)&wch, g_wch);
    cudaGetSymbolAddress((void**)&w3h, g_w3h);
    cudaGetSymbolAddress((void**)&w2h, g_w2h);
    cudaGetSymbolAddress((void**)&bn,  g_bn);

    // fork: weight prep on s_aux concurrent with activation transpose
    cudaEventRecord(ev0, 0);
    cudaStreamWaitEvent(s_aux, ev0, 0);
    prep_bn<<<1, 256, 0, s_aux>>>(g1, b1, m1, v1, g3, b3, m3, v3, g2, b2, m2, v2);
    reorder_w_f16<<<2304, 256, 0, s_aux>>>(w1, wch, 256, 9, 0);
    reorder_w_f16<<<1152, 256, 0, s_aux>>>(w_off, wch, 50, 9, 256);
    reorder_w_f16<<<6400, 256, 0, s_aux>>>(w3, w3h, 256, 25, 0);
    reorder_w_f16<<<2304, 256, 0, s_aux>>>(w2, w2h, 256, 9, 0);
    cudaEventRecord(evA, s_aux);

    transpose_cl<<<dim3(32, 8, 32), dim3(32, 8)>>>(x, xTh);
    cudaStreamWaitEvent(0, evA, 0);

    // offset conv (rows 256..383 of wch), implicit taps -> goff
    gemm_tc<<<dim3(1, 256), 256, GSMEM>>>(wch, xTh, KCA, 1, 256, 0,
                                          bn, bn + 256, b_off, nullptr,
                                          gout, nullptr, goff);
    // deformable sampling -> SB
    sampler_f16<<<102400, 256>>>(xTh, goff, SB);
    // conv1 (rows 0..255), implicit taps -> gout
    gemm_tc<<<dim3(2, 256), 256, GSMEM>>>(wch, xTh, KCA, 1, 0, 0,
                                          bn, bn + 256, b_off, nullptr,
                                          gout, nullptr, goff);
    // deform conv: xTh(NHWC fp16) = gout + relu(bn3(C)), smem-staged epilogue
    gemm_tc<<<dim3(2, 256), 256, GSMEM>>>(w3h, SB, KCB, 0, 0, 2,
                                          bn + 512, bn + 768, nullptr, gout,
                                          nullptr, xTh, nullptr);
    // conv2: relu(bn2(C) + x) -> out, implicit taps from xTh
    gemm_tc<<<dim3(2, 256), 256, GSMEM>>>(w2h, xTh, KCA, 1, 0, 3,
                                          bn + 1024, bn + 1280, nullptr, x,
                                          out, nullptr, nullptr);
}